// round 15
// baseline (speedup 1.0000x reference)
#include <cuda_runtime.h>
#include <cuda_bf16.h>
#include <math.h>

// ---------------- problem constants ----------------
#define S_LEN  4096
#define D_DIM  768
#define M_MEN  1024
#define K_CAND 32
#define PAIRS  (M_MEN * K_CAND)   // 32768
#define NROWS  (PAIRS * 2)        // 65536 token rows
#define NCAT   3840               // [wq|wk|wv|relik|uni] packed columns
#define NHEADS 8
#define DHEAD  96
#define CTX_W  10
#define FFH    3072

typedef __nv_bfloat16 bf16;

// ---------------- scratch (__device__ globals; no runtime allocs) ----------------
__device__ float g_mc[2048 * D_DIM];
__device__ __align__(16) bf16 g_mc_h[2048 * D_DIM];
__device__ __align__(16) bf16 g_mc_l[2048 * D_DIM];
__device__ __align__(16) bf16 g_cand_h[(size_t)PAIRS * D_DIM];
__device__ __align__(16) bf16 g_cand_l[(size_t)PAIRS * D_DIM];
__device__ __align__(16) bf16 g_Wtop_h[(size_t)NCAT * D_DIM];
__device__ __align__(16) bf16 g_Wtop_l[(size_t)NCAT * D_DIM];
__device__ __align__(16) bf16 g_Wbot_h[(size_t)NCAT * D_DIM];
__device__ __align__(16) bf16 g_Wbot_l[(size_t)NCAT * D_DIM];
__device__ float g_btop[NCAT];
__device__ float g_bbot[NCAT];
__device__ float g_w2bar[D_DIM];
__device__ float g_b2bar[1];
__device__ __align__(16) bf16 g_woT_h[D_DIM * D_DIM];
__device__ __align__(16) bf16 g_woT_l[D_DIM * D_DIM];
__device__ __align__(16) bf16 g_f1T_h[(size_t)FFH * D_DIM];
__device__ __align__(16) bf16 g_f1T_l[(size_t)FFH * D_DIM];
__device__ __align__(16) bf16 g_f2T_h[(size_t)D_DIM * FFH];
__device__ __align__(16) bf16 g_f2T_l[(size_t)D_DIM * FFH];
__device__ float g_Pcat[2048 * NCAT];
__device__ float g_Ccat[(size_t)PAIRS * NCAT];
__device__ __align__(16) bf16 g_O_h[(size_t)NROWS * D_DIM];
__device__ __align__(16) bf16 g_O_l[(size_t)NROWS * D_DIM];
__device__ float g_T[(size_t)NROWS * D_DIM];
__device__ float g_X1[(size_t)NROWS * D_DIM];
__device__ __align__(16) bf16 g_X1_h[(size_t)NROWS * D_DIM];
__device__ __align__(16) bf16 g_X1_l[(size_t)NROWS * D_DIM];
__device__ __align__(16) bf16 g_F_h[(size_t)NROWS * FFH];
__device__ __align__(16) bf16 g_F_l[(size_t)NROWS * FFH];
__device__ float g_G[(size_t)NROWS * D_DIM];

// ======================= helpers =======================
__device__ __forceinline__ unsigned smem_u32(const void* p) {
    unsigned a;
    asm("{ .reg .u64 t; cvta.to.shared.u64 t, %1; cvt.u32.u64 %0, t; }" : "=r"(a) : "l"(p));
    return a;
}

#define LDSM4(r, addr) \
    asm volatile("ldmatrix.sync.aligned.m8n8.x4.shared.b16 {%0,%1,%2,%3}, [%4];" \
        : "=r"((r)[0]), "=r"((r)[1]), "=r"((r)[2]), "=r"((r)[3]) : "r"(addr))

#define CP16(d, s) \
    asm volatile("cp.async.cg.shared.global [%0], [%1], 16;" :: "r"(d), "l"(s) : "memory")
#define CP_COMMIT() asm volatile("cp.async.commit_group;" ::: "memory")
#define CP_WAIT1()  asm volatile("cp.async.wait_group 1;" ::: "memory")
#define CP_WAIT0()  asm volatile("cp.async.wait_group 0;" ::: "memory")

__device__ __forceinline__ void mma_bf16(float* c, const unsigned* a, const unsigned* b) {
    asm volatile(
        "mma.sync.aligned.m16n8k16.row.col.f32.bf16.bf16.f32 "
        "{%0,%1,%2,%3}, {%4,%5,%6,%7}, {%8,%9}, {%0,%1,%2,%3};"
        : "+f"(c[0]), "+f"(c[1]), "+f"(c[2]), "+f"(c[3])
        : "r"(a[0]), "r"(a[1]), "r"(a[2]), "r"(a[3]), "r"(b[0]), "r"(b[1]));
}

// pack pair: hi = {trunc(x), trunc(y)}, lo = {rn(x-hix), rn(y-hiy)}
__device__ __forceinline__ void cvt_pair(float x, float y, unsigned& hi, unsigned& lo) {
    unsigned xu = __float_as_uint(x), yu = __float_as_uint(y);
    hi = __byte_perm(xu, yu, 0x7632);
    float xr = x - __uint_as_float(xu & 0xFFFF0000u);
    float yr = y - __uint_as_float(yu & 0xFFFF0000u);
    asm("cvt.rn.bf16x2.f32 %0, %1, %2;" : "=r"(lo) : "f"(yr), "f"(xr));
}

// scalar split
__device__ __forceinline__ void fsplit(float x, bf16& h, bf16& l) {
    unsigned xu = __float_as_uint(x);
    h = __ushort_as_bfloat16((unsigned short)(xu >> 16));
    l = __float2bfloat16(x - __uint_as_float(xu & 0xFFFF0000u));
}

// ======================= bf16x3 tensor-core GEMM (cp.async, 3-stage) =======================
// C[MM,NN] = A[MM,KK] @ Bt[NN,KK]^T (+bias), operands pre-split into hi/lo bf16 planes.
// mode: 0 = fp32 out, 1 = fp32 out + relu, 2 = bf16 hi/lo out + relu
// MM%128==0, NN%128==0, KK%32==0, KK/32 >= 2.
#define KSH     40                         // smem halves per row (32 data + 8 pad)
#define TILE_B  (128 * KSH * 2)            // 10240 B per plane
#define STAGE_B (4 * TILE_B)               // 40960 B per stage (Ahi,Alo,Bhi,Blo)
#define NSTAGE  3
#define TGEMM_SMEM (NSTAGE * STAGE_B)      // 122880 B

__global__ __launch_bounds__(256, 1) void tgemm_kernel(
    int MM, int NN, int KK,
    const bf16* __restrict__ Ah, const bf16* __restrict__ Al,
    const bf16* __restrict__ Bh, const bf16* __restrict__ Bl,
    const float* __restrict__ bias,
    float* __restrict__ C, bf16* __restrict__ Ch, bf16* __restrict__ Cl,
    int mode)
{
    extern __shared__ char sm[];
    unsigned sbase = smem_u32(sm);

    int tid = threadIdx.x;
    int lane = tid & 31;
    int wid = tid >> 5;
    int wm = wid & 3;          // 0..3 -> M
    int wn = wid >> 2;         // 0..1 -> N
    int row0 = blockIdx.y * 128;
    int col0 = blockIdx.x * 128;

    float acc[2][8][4];
#pragma unroll
    for (int i = 0; i < 2; i++)
#pragma unroll
        for (int j = 0; j < 8; j++)
#pragma unroll
            for (int q = 0; q < 4; q++) acc[i][j][q] = 0.f;

    // ldmatrix per-lane byte offsets (within a plane)
    unsigned offA = (unsigned)(((lane & 15) * KSH + ((lane >> 4) << 3)) * 2);
    unsigned offB = (unsigned)(((((lane >> 4) << 3) + (lane & 7)) * KSH + (((lane >> 3) & 1) << 3)) * 2);

    // cp.async staging: thread -> row (tid>>1), two 16B groups at k-cols {sc16, sc16+1}*8
    int srow = tid >> 1;               // 0..127
    int sc16 = (tid & 1) * 2;          // 0 or 2
    const bf16* pAh = Ah + (size_t)(row0 + srow) * KK + sc16 * 8;
    const bf16* pAl = Al + (size_t)(row0 + srow) * KK + sc16 * 8;
    const bf16* pBh = Bh + (size_t)(col0 + srow) * KK + sc16 * 8;
    const bf16* pBl = Bl + (size_t)(col0 + srow) * KK + sc16 * 8;
    unsigned doff = (unsigned)(srow * (KSH * 2) + sc16 * 16);

    int NC = KK >> 5;

#define ISSUE_CHUNK(kc, stg) do {                                         \
    unsigned _d = sbase + (unsigned)(stg) * STAGE_B + doff;               \
    size_t _ko = (size_t)(kc) * 32;                                       \
    CP16(_d,                       pAh + _ko);                            \
    CP16(_d + 16u,                 pAh + _ko + 8);                        \
    CP16(_d + TILE_B,              pAl + _ko);                            \
    CP16(_d + TILE_B + 16u,        pAl + _ko + 8);                        \
    CP16(_d + 2u * TILE_B,         pBh + _ko);                            \
    CP16(_d + 2u * TILE_B + 16u,   pBh + _ko + 8);                        \
    CP16(_d + 3u * TILE_B,         pBl + _ko);                            \
    CP16(_d + 3u * TILE_B + 16u,   pBl + _ko + 8);                        \
} while (0)

    ISSUE_CHUNK(0, 0); CP_COMMIT();
    ISSUE_CHUNK(1, 1); CP_COMMIT();

    int stage = 0, sp2 = 2;
    for (int kc = 0; kc < NC; kc++) {
        if (kc + 2 < NC) {
            CP_WAIT1();
            __syncthreads();
            ISSUE_CHUNK(kc + 2, sp2);
            CP_COMMIT();
        } else {
            CP_WAIT0();
            __syncthreads();
        }

        unsigned bufbase = sbase + (unsigned)stage * STAGE_B;
#pragma unroll
        for (int ks = 0; ks < 2; ks++) {
            unsigned a_hi[2][4], a_lo[2][4], b_hi[4][4], b_lo[4][4];
#pragma unroll
            for (int mt = 0; mt < 2; mt++) {
                unsigned ad = bufbase + (unsigned)((wm * 32 + mt * 16) * (KSH * 2)) +
                              (unsigned)(ks * 32) + offA;
                LDSM4(a_hi[mt], ad);
                LDSM4(a_lo[mt], ad + TILE_B);
            }
#pragma unroll
            for (int np = 0; np < 4; np++) {
                unsigned bd = bufbase + 2u * TILE_B +
                              (unsigned)((wn * 64 + np * 16) * (KSH * 2)) +
                              (unsigned)(ks * 32) + offB;
                LDSM4(b_hi[np], bd);
                LDSM4(b_lo[np], bd + TILE_B);
            }
#pragma unroll
            for (int mt = 0; mt < 2; mt++)
#pragma unroll
                for (int nt = 0; nt < 8; nt++) {
                    const unsigned* bh = &b_hi[nt >> 1][(nt & 1) * 2];
                    const unsigned* bl = &b_lo[nt >> 1][(nt & 1) * 2];
                    mma_bf16(acc[mt][nt], a_hi[mt], bh);
                    mma_bf16(acc[mt][nt], a_hi[mt], bl);
                    mma_bf16(acc[mt][nt], a_lo[mt], bh);
                }
        }
        __syncthreads();
        stage = (stage == NSTAGE - 1) ? 0 : stage + 1;
        sp2 = (sp2 == NSTAGE - 1) ? 0 : sp2 + 1;
    }

    // ---- epilogue ----
    int g = lane >> 2;
    int t2 = (lane & 3) * 2;
#pragma unroll
    for (int mt = 0; mt < 2; mt++) {
        int r = row0 + wm * 32 + mt * 16 + g;
#pragma unroll
        for (int nt = 0; nt < 8; nt++) {
            int c = col0 + wn * 64 + nt * 8 + t2;
            float b0 = bias[c], b1 = bias[c + 1];
            float v0 = acc[mt][nt][0] + b0;
            float v1 = acc[mt][nt][1] + b1;
            float v2 = acc[mt][nt][2] + b0;
            float v3 = acc[mt][nt][3] + b1;
            if (mode != 0) {
                v0 = fmaxf(v0, 0.f); v1 = fmaxf(v1, 0.f);
                v2 = fmaxf(v2, 0.f); v3 = fmaxf(v3, 0.f);
            }
            if (mode == 2) {
                unsigned h01, l01, h23, l23;
                cvt_pair(v0, v1, h01, l01);
                cvt_pair(v2, v3, h23, l23);
                *(unsigned*)(Ch + (size_t)r * NN + c) = h01;
                *(unsigned*)(Cl + (size_t)r * NN + c) = l01;
                *(unsigned*)(Ch + (size_t)(r + 8) * NN + c) = h23;
                *(unsigned*)(Cl + (size_t)(r + 8) * NN + c) = l23;
            } else {
                *(float2*)(C + (size_t)r * NN + c) = make_float2(v0, v1);
                *(float2*)(C + (size_t)(r + 8) * NN + c) = make_float2(v2, v3);
            }
        }
    }
}

// ---------------- mention & context pooling (fp32 + hi/lo planes) ----------------
__global__ void mention_ctx_kernel(const float* __restrict__ txt,
                                   const int* __restrict__ starts,
                                   const int* __restrict__ lens) {
    int m = blockIdx.x;
    int d = threadIdx.x;
    int s = starts[m], L = lens[m], e = s + L;
    float acc = 0.f;
    for (int r = s; r <= e; r++) acc += txt[(size_t)r * D_DIM + d];
    float mv = acc / (float)(L + 1);
    size_t i0 = (size_t)m * D_DIM + d;
    g_mc[i0] = mv;
    fsplit(mv, g_mc_h[i0], g_mc_l[i0]);

    int cs = s - CTX_W; if (cs < 0) cs = 0;
    int ce = e + CTX_W; if (ce > S_LEN - 1) ce = S_LEN - 1;
    float a2 = 0.f;
    for (int r = cs; r < ce; r++) a2 += txt[(size_t)r * D_DIM + d];
    float cv = a2 / (float)(ce - cs);
    size_t i1 = (size_t)(M_MEN + m) * D_DIM + d;
    g_mc[i1] = cv;
    fsplit(cv, g_mc_h[i1], g_mc_l[i1]);
}

// ---------------- candidate fp32 -> hi/lo planes ----------------
__global__ void cand_hl_kernel(const float* __restrict__ cand) {
    size_t total4 = (size_t)PAIRS * D_DIM / 4;
    for (size_t i = blockIdx.x * blockDim.x + threadIdx.x; i < total4;
         i += (size_t)gridDim.x * blockDim.x) {
        float4 v = ((const float4*)cand)[i];
        unsigned h0, l0, h1, l1;
        cvt_pair(v.x, v.y, h0, l0);
        cvt_pair(v.z, v.w, h1, l1);
        ((uint2*)g_cand_h)[i] = make_uint2(h0, h1);
        ((uint2*)g_cand_l)[i] = make_uint2(l0, l1);
    }
}

// ---------------- pack concatenated weights (transposed hi/lo planes) ----------------
__global__ void pack_w_kernel(const float* __restrict__ wq, const float* __restrict__ wk,
                              const float* __restrict__ wv, const float* __restrict__ rw1,
                              const float* __restrict__ uw1) {
    size_t total = (size_t)D_DIM * NCAT;
    for (size_t idx = blockIdx.x * blockDim.x + threadIdx.x; idx < total;
         idx += (size_t)gridDim.x * blockDim.x) {
        int c = (int)(idx / D_DIM);
        int k = (int)(idx % D_DIM);
        int seg = c / D_DIM;
        int j = c - seg * D_DIM;
        float top, bot;
        if (seg == 0)      { top = bot = wq[k * D_DIM + j]; }
        else if (seg == 1) { top = bot = wk[k * D_DIM + j]; }
        else if (seg == 2) { top = bot = wv[k * D_DIM + j]; }
        else if (seg == 3) { top = rw1[k * D_DIM + j]; bot = rw1[(D_DIM + k) * D_DIM + j]; }
        else               { top = uw1[k * D_DIM + j]; bot = uw1[(D_DIM + k) * D_DIM + j]; }
        fsplit(top, g_Wtop_h[idx], g_Wtop_l[idx]);
        fsplit(bot, g_Wbot_h[idx], g_Wbot_l[idx]);
    }
}

__global__ void pack_b_kernel(const float* __restrict__ bq, const float* __restrict__ bk,
                              const float* __restrict__ bv, const float* __restrict__ rb1,
                              const float* __restrict__ ub1, const float* __restrict__ uw2,
                              const float* __restrict__ ub2) {
    int idx = blockIdx.x * blockDim.x + threadIdx.x;
    if (idx < NCAT) {
        int seg = idx / D_DIM;
        int j = idx - seg * D_DIM;
        float qb = (seg == 0) ? bq[j] : (seg == 1) ? bk[j] : (seg == 2) ? bv[j] : 0.f;
        g_btop[idx] = qb;
        g_bbot[idx] = (seg < 3) ? qb : (seg == 3) ? rb1[j] : ub1[j];
    }
    if (idx < D_DIM) {
        float s = 0.f;
        for (int j2 = 0; j2 < D_DIM; j2++) s += uw2[idx * D_DIM + j2];
        g_w2bar[idx] = s / (float)D_DIM;
    }
    if (idx == 0) {
        float s = 0.f;
        for (int j2 = 0; j2 < D_DIM; j2++) s += ub2[j2];
        g_b2bar[0] = s / (float)D_DIM;
    }
}

// ---------------- tiled transpose -> hi/lo planes ----------------
__global__ void transpose_hl_kernel(const float* __restrict__ in,
                                    bf16* __restrict__ outh, bf16* __restrict__ outl,
                                    int R, int Ccols) {
    __shared__ float t[32][33];
    int r0 = blockIdx.y * 32, c0 = blockIdx.x * 32;
    int x = threadIdx.x, y = threadIdx.y;   // (32, 8)
#pragma unroll
    for (int j = 0; j < 32; j += 8)
        t[y + j][x] = in[(size_t)(r0 + y + j) * Ccols + c0 + x];
    __syncthreads();
#pragma unroll
    for (int j = 0; j < 32; j += 8) {
        size_t o = (size_t)(c0 + y + j) * R + r0 + x;
        fsplit(t[x][y + j], outh[o], outl[o]);
    }
}

// ---------------- relik + unirel fused reduction ----------------
__global__ void relik_uni_kernel(const float* __restrict__ rw2,
                                 const float* __restrict__ rb2,
                                 float* __restrict__ out) {
    int p = blockIdx.x;
    int m = p >> 5;
    const float* Prel = g_Pcat + (size_t)m * NCAT + 2304;
    const float* Crel = g_Ccat + (size_t)p * NCAT + 2304;
    const float* Puni = g_Pcat + (size_t)(M_MEN + m) * NCAT + 3072;
    const float* Cuni = g_Ccat + (size_t)p * NCAT + 3072;
    int tid = threadIdx.x;
    float sr = 0.f, su = 0.f;
    for (int i = tid; i < D_DIM; i += 256) {
        sr += fmaxf(Prel[i] + Crel[i], 0.f) * rw2[i];
        su += fmaxf(Puni[i] + Cuni[i], 0.f) * g_w2bar[i];
    }
    __shared__ float r1[8], r2[8];
#pragma unroll
    for (int sh = 16; sh; sh >>= 1) {
        sr += __shfl_down_sync(0xffffffffu, sr, sh);
        su += __shfl_down_sync(0xffffffffu, su, sh);
    }
    if ((tid & 31) == 0) { r1[tid >> 5] = sr; r2[tid >> 5] = su; }
    __syncthreads();
    if (tid == 0) {
        float a = 0.f, b = 0.f;
#pragma unroll
        for (int i = 0; i < 8; i++) { a += r1[i]; b += r2[i]; }
        out[p] = a + rb2[0];
        out[2 * PAIRS + p] = 1.f / (1.f + expf(-(b + g_b2bar[0])));
    }
}

// ---------------- fused 2-token attention (writes O hi/lo) ----------------
__global__ void attn_kernel() {
    int p = blockIdx.x;
    int m = p >> 5;
    int w = threadIdx.x >> 5;
    int l = threadIdx.x & 31;
    const float* P0 = g_Pcat + (size_t)m * NCAT;
    const float* C1 = g_Ccat + (size_t)p * NCAT;
    int off = w * DHEAD;
    float q0v[3], k0v[3], v0v[3], q1v[3], k1v[3], v1v[3];
#pragma unroll
    for (int j = 0; j < 3; j++) {
        int d = off + l + 32 * j;
        q0v[j] = P0[d]; k0v[j] = P0[768 + d]; v0v[j] = P0[1536 + d];
        q1v[j] = C1[d]; k1v[j] = C1[768 + d]; v1v[j] = C1[1536 + d];
    }
    float s00 = 0.f, s01 = 0.f, s10 = 0.f, s11 = 0.f;
#pragma unroll
    for (int j = 0; j < 3; j++) {
        s00 += q0v[j] * k0v[j];
        s01 += q0v[j] * k1v[j];
        s10 += q1v[j] * k0v[j];
        s11 += q1v[j] * k1v[j];
    }
#pragma unroll
    for (int sh = 16; sh; sh >>= 1) {
        s00 += __shfl_xor_sync(0xffffffffu, s00, sh);
        s01 += __shfl_xor_sync(0xffffffffu, s01, sh);
        s10 += __shfl_xor_sync(0xffffffffu, s10, sh);
        s11 += __shfl_xor_sync(0xffffffffu, s11, sh);
    }
    const float sc = 0.10206207261596575f;   // 1/sqrt(96)
    float w01 = 1.f / (1.f + expf((s00 - s01) * sc));
    float w00 = 1.f - w01;
    float w11 = 1.f / (1.f + expf((s10 - s11) * sc));
    float w10 = 1.f - w11;
    size_t r0 = (size_t)(2 * p) * D_DIM;
#pragma unroll
    for (int j = 0; j < 3; j++) {
        int d = off + l + 32 * j;
        float o0 = w00 * v0v[j] + w01 * v1v[j];
        float o1 = w10 * v0v[j] + w11 * v1v[j];
        fsplit(o0, g_O_h[r0 + d], g_O_l[r0 + d]);
        fsplit(o1, g_O_h[r0 + D_DIM + d], g_O_l[r0 + D_DIM + d]);
    }
}

// ---------------- residual + LN1 (writes X1 fp32 + hi/lo) ----------------
__global__ void ln1_kernel(const float* __restrict__ cand,
                           const float* __restrict__ g, const float* __restrict__ b) {
    int r = blockIdx.x;
    int p = r >> 1, t = r & 1, m = p >> 5;
    const float* xrow = t ? (cand + (size_t)p * D_DIM) : (g_mc + (size_t)m * D_DIM);
    const float* trow = g_T + (size_t)r * D_DIM;
    int tid = threadIdx.x;
    float v[3];
    float s = 0.f, s2 = 0.f;
#pragma unroll
    for (int j = 0; j < 3; j++) {
        int i = tid + j * 256;
        v[j] = xrow[i] + trow[i];
        s += v[j];
        s2 += v[j] * v[j];
    }
    __shared__ float r1[8], r2[8];
#pragma unroll
    for (int sh = 16; sh; sh >>= 1) {
        s += __shfl_down_sync(0xffffffffu, s, sh);
        s2 += __shfl_down_sync(0xffffffffu, s2, sh);
    }
    if ((tid & 31) == 0) { r1[tid >> 5] = s; r2[tid >> 5] = s2; }
    __syncthreads();
    float tot = 0.f, tot2 = 0.f;
#pragma unroll
    for (int i = 0; i < 8; i++) { tot += r1[i]; tot2 += r2[i]; }
    float mean = tot * (1.f / 768.f);
    float var = tot2 * (1.f / 768.f) - mean * mean;
    float inv = rsqrtf(var + 1e-5f);
    size_t base = (size_t)r * D_DIM;
#pragma unroll
    for (int j = 0; j < 3; j++) {
        int i = tid + j * 256;
        float xv = (v[j] - mean) * inv * g[i] + b[i];
        g_X1[base + i] = xv;
        fsplit(xv, g_X1_h[base + i], g_X1_l[base + i]);
    }
}

// ---------------- residual + LN2 + cosine ----------------
__global__ void ln2_cos_kernel(const float* __restrict__ g, const float* __restrict__ b,
                               float* __restrict__ out) {
    int p = blockIdx.x;
    int tid = threadIdx.x;
    __shared__ float e[2][D_DIM];
    __shared__ float r1[8], r2[8], r3[8];
    for (int t = 0; t < 2; t++) {
        size_t r = (size_t)2 * p + t;
        const float* x1 = g_X1 + r * D_DIM;
        const float* gr = g_G + r * D_DIM;
        float v[3];
        float s = 0.f, s2 = 0.f;
#pragma unroll
        for (int j = 0; j < 3; j++) {
            int i = tid + j * 256;
            v[j] = x1[i] + gr[i];
            s += v[j];
            s2 += v[j] * v[j];
        }
#pragma unroll
        for (int sh = 16; sh; sh >>= 1) {
            s += __shfl_down_sync(0xffffffffu, s, sh);
            s2 += __shfl_down_sync(0xffffffffu, s2, sh);
        }
        if ((tid & 31) == 0) { r1[tid >> 5] = s; r2[tid >> 5] = s2; }
        __syncthreads();
        float tot = 0.f, tot2 = 0.f;
#pragma unroll
        for (int i = 0; i < 8; i++) { tot += r1[i]; tot2 += r2[i]; }
        float mean = tot * (1.f / 768.f);
        float var = tot2 * (1.f / 768.f) - mean * mean;
        float inv = rsqrtf(var + 1e-5f);
#pragma unroll
        for (int j = 0; j < 3; j++) {
            int i = tid + j * 256;
            e[t][i] = (v[j] - mean) * inv * g[i] + b[i];
        }
        __syncthreads();
    }
    float d = 0.f, n0 = 0.f, n1 = 0.f;
#pragma unroll
    for (int j = 0; j < 3; j++) {
        int i = tid + j * 256;
        float a = e[0][i], c = e[1][i];
        d += a * c;
        n0 += a * a;
        n1 += c * c;
    }
#pragma unroll
    for (int sh = 16; sh; sh >>= 1) {
        d += __shfl_down_sync(0xffffffffu, d, sh);
        n0 += __shfl_down_sync(0xffffffffu, n0, sh);
        n1 += __shfl_down_sync(0xffffffffu, n1, sh);
    }
    if ((tid & 31) == 0) { r1[tid >> 5] = d; r2[tid >> 5] = n0; r3[tid >> 5] = n1; }
    __syncthreads();
    if (tid == 0) {
        float td = 0.f, t0 = 0.f, t1 = 0.f;
#pragma unroll
        for (int i = 0; i < 8; i++) { td += r1[i]; t0 += r2[i]; t1 += r3[i]; }
        float na = fmaxf(sqrtf(t0), 1e-8f);
        float nb = fmaxf(sqrtf(t1), 1e-8f);
        out[PAIRS + p] = td / (na * nb);
    }
}

// ---------------- host launcher ----------------
extern "C" void kernel_launch(void* const* d_in, const int* in_sizes, int n_in,
                              void* d_out, int out_size) {
    const float* txt      = (const float*)d_in[0];
    const float* cand     = (const float*)d_in[1];
    const int*   starts   = (const int*)d_in[2];
    const int*   lens     = (const int*)d_in[3];
    const float* relik_w1 = (const float*)d_in[4];
    const float* relik_b1 = (const float*)d_in[5];
    const float* relik_w2 = (const float*)d_in[6];
    const float* relik_b2 = (const float*)d_in[7];
    const float* wq  = (const float*)d_in[8];
    const float* bq  = (const float*)d_in[9];
    const float* wk  = (const float*)d_in[10];
    const float* bk  = (const float*)d_in[11];
    const float* wv  = (const float*)d_in[12];
    const float* bv  = (const float*)d_in[13];
    const float* wo  = (const float*)d_in[14];
    const float* bo  = (const float*)d_in[15];
    const float* ln1_g = (const float*)d_in[16];
    const float* ln1_b = (const float*)d_in[17];
    const float* ffn_w1 = (const float*)d_in[18];
    const float* ffn_b1 = (const float*)d_in[19];
    const float* ffn_w2 = (const float*)d_in[20];
    const float* ffn_b2 = (const float*)d_in[21];
    const float* ln2_g = (const float*)d_in[22];
    const float* ln2_b = (const float*)d_in[23];
    const float* uni_w1 = (const float*)d_in[24];
    const float* uni_b1 = (const float*)d_in[25];
    const float* uni_w2 = (const float*)d_in[26];
    const float* uni_b2 = (const float*)d_in[27];
    float* out = (float*)d_out;

    float *p_btop, *p_bbot, *p_Pcat, *p_Ccat, *p_T, *p_X1, *p_G;
    bf16 *p_mc_h, *p_mc_l, *p_cand_h, *p_cand_l;
    bf16 *p_Wtop_h, *p_Wtop_l, *p_Wbot_h, *p_Wbot_l;
    bf16 *p_woT_h, *p_woT_l, *p_f1T_h, *p_f1T_l, *p_f2T_h, *p_f2T_l;
    bf16 *p_O_h, *p_O_l, *p_X1_h, *p_X1_l, *p_F_h, *p_F_l;
    cudaGetSymbolAddress((void**)&p_btop,   g_btop);
    cudaGetSymbolAddress((void**)&p_bbot,   g_bbot);
    cudaGetSymbolAddress((void**)&p_Pcat,   g_Pcat);
    cudaGetSymbolAddress((void**)&p_Ccat,   g_Ccat);
    cudaGetSymbolAddress((void**)&p_T,      g_T);
    cudaGetSymbolAddress((void**)&p_X1,     g_X1);
    cudaGetSymbolAddress((void**)&p_G,      g_G);
    cudaGetSymbolAddress((void**)&p_mc_h,   g_mc_h);
    cudaGetSymbolAddress((void**)&p_mc_l,   g_mc_l);
    cudaGetSymbolAddress((void**)&p_cand_h, g_cand_h);
    cudaGetSymbolAddress((void**)&p_cand_l, g_cand_l);
    cudaGetSymbolAddress((void**)&p_Wtop_h, g_Wtop_h);
    cudaGetSymbolAddress((void**)&p_Wtop_l, g_Wtop_l);
    cudaGetSymbolAddress((void**)&p_Wbot_h, g_Wbot_h);
    cudaGetSymbolAddress((void**)&p_Wbot_l, g_Wbot_l);
    cudaGetSymbolAddress((void**)&p_woT_h,  g_woT_h);
    cudaGetSymbolAddress((void**)&p_woT_l,  g_woT_l);
    cudaGetSymbolAddress((void**)&p_f1T_h,  g_f1T_h);
    cudaGetSymbolAddress((void**)&p_f1T_l,  g_f1T_l);
    cudaGetSymbolAddress((void**)&p_f2T_h,  g_f2T_h);
    cudaGetSymbolAddress((void**)&p_f2T_l,  g_f2T_l);
    cudaGetSymbolAddress((void**)&p_O_h,    g_O_h);
    cudaGetSymbolAddress((void**)&p_O_l,    g_O_l);
    cudaGetSymbolAddress((void**)&p_X1_h,   g_X1_h);
    cudaGetSymbolAddress((void**)&p_X1_l,   g_X1_l);
    cudaGetSymbolAddress((void**)&p_F_h,    g_F_h);
    cudaGetSymbolAddress((void**)&p_F_l,    g_F_l);

    cudaFuncSetAttribute(tgemm_kernel,
                         cudaFuncAttributeMaxDynamicSharedMemorySize, TGEMM_SMEM);

    // 1. pooling + operand prep
    mention_ctx_kernel<<<M_MEN, D_DIM>>>(txt, starts, lens);
    cand_hl_kernel<<<4096, 256>>>(cand);
    pack_w_kernel<<<4096, 256>>>(wq, wk, wv, relik_w1, uni_w1);
    pack_b_kernel<<<15, 256>>>(bq, bk, bv, relik_b1, uni_b1, uni_w2, uni_b2);
    transpose_hl_kernel<<<dim3(D_DIM / 32, D_DIM / 32), dim3(32, 8)>>>(wo, p_woT_h, p_woT_l, D_DIM, D_DIM);
    transpose_hl_kernel<<<dim3(FFH / 32, D_DIM / 32), dim3(32, 8)>>>(ffn_w1, p_f1T_h, p_f1T_l, D_DIM, FFH);
    transpose_hl_kernel<<<dim3(D_DIM / 32, FFH / 32), dim3(32, 8)>>>(ffn_w2, p_f2T_h, p_f2T_l, FFH, D_DIM);

    // 2. projections
    tgemm_kernel<<<dim3(NCAT / 128, 2048 / 128), 256, TGEMM_SMEM>>>(
        2048, NCAT, D_DIM, p_mc_h, p_mc_l, p_Wtop_h, p_Wtop_l, p_btop,
        p_Pcat, nullptr, nullptr, 0);
    tgemm_kernel<<<dim3(NCAT / 128, PAIRS / 128), 256, TGEMM_SMEM>>>(
        PAIRS, NCAT, D_DIM, p_cand_h, p_cand_l, p_Wbot_h, p_Wbot_l, p_bbot,
        p_Ccat, nullptr, nullptr, 0);

    // 3. relik + unirel heads
    relik_uni_kernel<<<PAIRS, 256>>>(relik_w2, relik_b2, out);

    // 4. attention + transformer block
    attn_kernel<<<PAIRS, 256>>>();
    tgemm_kernel<<<dim3(D_DIM / 128, NROWS / 128), 256, TGEMM_SMEM>>>(
        NROWS, D_DIM, D_DIM, p_O_h, p_O_l, p_woT_h, p_woT_l, bo,
        p_T, nullptr, nullptr, 0);
    ln1_kernel<<<NROWS, 256>>>(cand, ln1_g, ln1_b);
    tgemm_kernel<<<dim3(FFH / 128, NROWS / 128), 256, TGEMM_SMEM>>>(
        NROWS, FFH, D_DIM, p_X1_h, p_X1_l, p_f1T_h, p_f1T_l, ffn_b1,
        nullptr, p_F_h, p_F_l, 2);
    tgemm_kernel<<<dim3(D_DIM / 128, NROWS / 128), 256, TGEMM_SMEM>>>(
        NROWS, D_DIM, FFH, p_F_h, p_F_l, p_f2T_h, p_f2T_l, ffn_b2,
        p_G, nullptr, nullptr, 0);

    // 5. LN2 + cosine
    ln2_cos_kernel<<<PAIRS, 256>>>(ln2_g, ln2_b, out);
}

// round 16
// speedup vs baseline: 1.1136x; 1.1136x over previous
#include <cuda_runtime.h>
#include <cuda_bf16.h>
#include <math.h>

// ---------------- problem constants ----------------
#define S_LEN  4096
#define D_DIM  768
#define M_MEN  1024
#define K_CAND 32
#define PAIRS  (M_MEN * K_CAND)   // 32768
#define NROWS  (PAIRS * 2)        // 65536 token rows
#define NCAT   3840               // [wq|wk|wv|relik|uni] packed columns
#define NHEADS 8
#define DHEAD  96
#define CTX_W  10
#define FFH    3072

// ---------------- scratch (__device__ globals; no runtime allocs) ----------------
__device__ float g_mc[2048 * D_DIM];
__device__ float g_Wtop[(size_t)NCAT * D_DIM];   // transposed: [NCAT, D]
__device__ float g_Wbot[(size_t)NCAT * D_DIM];   // transposed: [NCAT, D]
__device__ float g_btop[NCAT];
__device__ float g_bbot[NCAT];
__device__ float g_w2bar[D_DIM];
__device__ float g_b2bar[1];
__device__ float g_woT[D_DIM * D_DIM];           // [N=768, K=768]
__device__ float g_f1T[(size_t)FFH * D_DIM];     // [N=3072, K=768]
__device__ float g_f2T[(size_t)D_DIM * FFH];     // [N=768, K=3072]
__device__ float g_Pcat[2048 * NCAT];
__device__ float g_Ccat[(size_t)PAIRS * NCAT];
__device__ float g_O[(size_t)NROWS * D_DIM];
__device__ float g_T[(size_t)NROWS * D_DIM];
__device__ float g_X1[(size_t)NROWS * D_DIM];
__device__ float g_F[(size_t)NROWS * FFH];
__device__ float g_G[(size_t)NROWS * D_DIM];

// ======================= helpers =======================
__device__ __forceinline__ unsigned smem_u32(const void* p) {
    unsigned a;
    asm("{ .reg .u64 t; cvta.to.shared.u64 t, %1; cvt.u32.u64 %0, t; }" : "=r"(a) : "l"(p));
    return a;
}

#define LDSM4(r, addr) \
    asm volatile("ldmatrix.sync.aligned.m8n8.x4.shared.b16 {%0,%1,%2,%3}, [%4];" \
        : "=r"((r)[0]), "=r"((r)[1]), "=r"((r)[2]), "=r"((r)[3]) : "r"(addr))

#define STS128(r0, r1, r2, r3, addr) \
    asm volatile("st.shared.v4.b32 [%0], {%1, %2, %3, %4};" \
                 :: "r"(addr), "r"(r0), "r"(r1), "r"(r2), "r"(r3) : "memory")

__device__ __forceinline__ void mma_bf16(float* c, const unsigned* a, const unsigned* b) {
    asm volatile(
        "mma.sync.aligned.m16n8k16.row.col.f32.bf16.bf16.f32 "
        "{%0,%1,%2,%3}, {%4,%5,%6,%7}, {%8,%9}, {%0,%1,%2,%3};"
        : "+f"(c[0]), "+f"(c[1]), "+f"(c[2]), "+f"(c[3])
        : "r"(a[0]), "r"(a[1]), "r"(a[2]), "r"(a[3]), "r"(b[0]), "r"(b[1]));
}

// split x,y into bf16 hi (truncated) pair + bf16 lo (residual, RN) pair
__device__ __forceinline__ void cvt_pair(float x, float y, unsigned& hi, unsigned& lo) {
    unsigned xu = __float_as_uint(x), yu = __float_as_uint(y);
    hi = __byte_perm(xu, yu, 0x7632);          // {bf16_trunc(x), bf16_trunc(y)}
    float xr = x - __uint_as_float(xu & 0xFFFF0000u);
    float yr = y - __uint_as_float(yu & 0xFFFF0000u);
    asm("cvt.rn.bf16x2.f32 %0, %1, %2;" : "=r"(lo) : "f"(yr), "f"(xr));
}

// ======================= bf16x3 tensor-core GEMM (R7-proven form) =======================
// C[MM,NN] = A[MM,KK] @ Bt[NN,KK]^T (+bias)(+relu).
// MM%128==0, NN%128==0, KK%32==0.
#define KSH     40                         // smem halves per row (32 data + 8 pad)
#define TILE_B  (128 * KSH * 2)            // 10240 B per plane
#define BUF_B   (4 * TILE_B)               // Ahi, Alo, Bhi, Blo
#define TGEMM_SMEM (2 * BUF_B)             // 81920 B double-buffered

__global__ __launch_bounds__(256, 1) void tgemm_kernel(
    int MM, int NN, int KK,
    const float* __restrict__ A, const float* __restrict__ Bt,
    const float* __restrict__ bias, float* __restrict__ C, int do_relu)
{
    extern __shared__ char sm[];
    unsigned sbase = smem_u32(sm);

    int tid = threadIdx.x;
    int lane = tid & 31;
    int wid = tid >> 5;
    int wm = wid & 3;          // 0..3 -> M
    int wn = wid >> 2;         // 0..1 -> N
    int row0 = blockIdx.y * 128;
    int col0 = blockIdx.x * 128;

    float acc[2][8][4];
#pragma unroll
    for (int i = 0; i < 2; i++)
#pragma unroll
        for (int j = 0; j < 8; j++)
#pragma unroll
            for (int q = 0; q < 4; q++) acc[i][j][q] = 0.f;

    // ldmatrix per-lane byte offsets (within a plane)
    unsigned offA = (unsigned)(((lane & 15) * KSH + ((lane >> 4) << 3)) * 2);
    unsigned offB = (unsigned)(((((lane >> 4) << 3) + (lane & 7)) * KSH + (((lane >> 3) & 1) << 3)) * 2);

    // staging: thread covers row srow, 16 consecutive k-cols
    int srow = tid >> 1;
    int scb = (tid & 1) * 16;
    const float* Ag = A + (size_t)(row0 + srow) * KK + scb;
    const float* Bg = Bt + (size_t)(col0 + srow) * KK + scb;
    unsigned stoff = (unsigned)((srow * KSH + scb) * 2);

    int NC = KK >> 5;
    float4 ra[4], rb[4];

    // ---- prologue: load chunk 0 ----
#pragma unroll
    for (int j = 0; j < 4; j++) {
        ra[j] = *(const float4*)(Ag + 4 * j);
        rb[j] = *(const float4*)(Bg + 4 * j);
    }
    {
        unsigned h[8], l[8];
        unsigned dst = sbase + stoff;
        cvt_pair(ra[0].x, ra[0].y, h[0], l[0]); cvt_pair(ra[0].z, ra[0].w, h[1], l[1]);
        cvt_pair(ra[1].x, ra[1].y, h[2], l[2]); cvt_pair(ra[1].z, ra[1].w, h[3], l[3]);
        cvt_pair(ra[2].x, ra[2].y, h[4], l[4]); cvt_pair(ra[2].z, ra[2].w, h[5], l[5]);
        cvt_pair(ra[3].x, ra[3].y, h[6], l[6]); cvt_pair(ra[3].z, ra[3].w, h[7], l[7]);
        STS128(h[0], h[1], h[2], h[3], dst);
        STS128(h[4], h[5], h[6], h[7], dst + 16u);
        STS128(l[0], l[1], l[2], l[3], dst + TILE_B);
        STS128(l[4], l[5], l[6], l[7], dst + TILE_B + 16u);
        cvt_pair(rb[0].x, rb[0].y, h[0], l[0]); cvt_pair(rb[0].z, rb[0].w, h[1], l[1]);
        cvt_pair(rb[1].x, rb[1].y, h[2], l[2]); cvt_pair(rb[1].z, rb[1].w, h[3], l[3]);
        cvt_pair(rb[2].x, rb[2].y, h[4], l[4]); cvt_pair(rb[2].z, rb[2].w, h[5], l[5]);
        cvt_pair(rb[3].x, rb[3].y, h[6], l[6]); cvt_pair(rb[3].z, rb[3].w, h[7], l[7]);
        STS128(h[0], h[1], h[2], h[3], dst + 2u * TILE_B);
        STS128(h[4], h[5], h[6], h[7], dst + 2u * TILE_B + 16u);
        STS128(l[0], l[1], l[2], l[3], dst + 3u * TILE_B);
        STS128(l[4], l[5], l[6], l[7], dst + 3u * TILE_B + 16u);
    }
    __syncthreads();

    for (int kc = 0; kc < NC; kc++) {
        unsigned bufbase = sbase + (unsigned)(kc & 1) * BUF_B;
        bool more = (kc + 1 < NC);
        if (more) {
#pragma unroll
            for (int j = 0; j < 4; j++) {
                ra[j] = *(const float4*)(Ag + (kc + 1) * 32 + 4 * j);
                rb[j] = *(const float4*)(Bg + (kc + 1) * 32 + 4 * j);
            }
        }
        // ---- compute from bufbase ----
#pragma unroll
        for (int ks = 0; ks < 2; ks++) {
            unsigned a_hi[2][4], a_lo[2][4], b_hi[4][4], b_lo[4][4];
#pragma unroll
            for (int mt = 0; mt < 2; mt++) {
                unsigned ad = bufbase + (unsigned)((wm * 32 + mt * 16) * (KSH * 2)) +
                              (unsigned)(ks * 32) + offA;
                LDSM4(a_hi[mt], ad);
                LDSM4(a_lo[mt], ad + TILE_B);
            }
#pragma unroll
            for (int np = 0; np < 4; np++) {
                unsigned bd = bufbase + 2u * TILE_B +
                              (unsigned)((wn * 64 + np * 16) * (KSH * 2)) +
                              (unsigned)(ks * 32) + offB;
                LDSM4(b_hi[np], bd);
                LDSM4(b_lo[np], bd + TILE_B);
            }
#pragma unroll
            for (int mt = 0; mt < 2; mt++)
#pragma unroll
                for (int nt = 0; nt < 8; nt++) {
                    const unsigned* bh = &b_hi[nt >> 1][(nt & 1) * 2];
                    const unsigned* bl = &b_lo[nt >> 1][(nt & 1) * 2];
                    mma_bf16(acc[mt][nt], a_hi[mt], bh);
                    mma_bf16(acc[mt][nt], a_hi[mt], bl);
                    mma_bf16(acc[mt][nt], a_lo[mt], bh);
                }
        }
        // ---- store next chunk into other buffer ----
        if (more) {
            unsigned h[8], l[8];
            unsigned dst = sbase + (unsigned)((kc + 1) & 1) * BUF_B + stoff;
            cvt_pair(ra[0].x, ra[0].y, h[0], l[0]); cvt_pair(ra[0].z, ra[0].w, h[1], l[1]);
            cvt_pair(ra[1].x, ra[1].y, h[2], l[2]); cvt_pair(ra[1].z, ra[1].w, h[3], l[3]);
            cvt_pair(ra[2].x, ra[2].y, h[4], l[4]); cvt_pair(ra[2].z, ra[2].w, h[5], l[5]);
            cvt_pair(ra[3].x, ra[3].y, h[6], l[6]); cvt_pair(ra[3].z, ra[3].w, h[7], l[7]);
            STS128(h[0], h[1], h[2], h[3], dst);
            STS128(h[4], h[5], h[6], h[7], dst + 16u);
            STS128(l[0], l[1], l[2], l[3], dst + TILE_B);
            STS128(l[4], l[5], l[6], l[7], dst + TILE_B + 16u);
            cvt_pair(rb[0].x, rb[0].y, h[0], l[0]); cvt_pair(rb[0].z, rb[0].w, h[1], l[1]);
            cvt_pair(rb[1].x, rb[1].y, h[2], l[2]); cvt_pair(rb[1].z, rb[1].w, h[3], l[3]);
            cvt_pair(rb[2].x, rb[2].y, h[4], l[4]); cvt_pair(rb[2].z, rb[2].w, h[5], l[5]);
            cvt_pair(rb[3].x, rb[3].y, h[6], l[6]); cvt_pair(rb[3].z, rb[3].w, h[7], l[7]);
            STS128(h[0], h[1], h[2], h[3], dst + 2u * TILE_B);
            STS128(h[4], h[5], h[6], h[7], dst + 2u * TILE_B + 16u);
            STS128(l[0], l[1], l[2], l[3], dst + 3u * TILE_B);
            STS128(l[4], l[5], l[6], l[7], dst + 3u * TILE_B + 16u);
        }
        __syncthreads();
    }

    // ---- epilogue: bias (+relu), direct global store ----
    int g = lane >> 2;
    int t2 = (lane & 3) * 2;
#pragma unroll
    for (int mt = 0; mt < 2; mt++) {
        int r = row0 + wm * 32 + mt * 16 + g;
#pragma unroll
        for (int nt = 0; nt < 8; nt++) {
            int c = col0 + wn * 64 + nt * 8 + t2;
            float b0 = bias[c], b1 = bias[c + 1];
            float v0 = acc[mt][nt][0] + b0;
            float v1 = acc[mt][nt][1] + b1;
            float v2 = acc[mt][nt][2] + b0;
            float v3 = acc[mt][nt][3] + b1;
            if (do_relu) {
                v0 = fmaxf(v0, 0.f); v1 = fmaxf(v1, 0.f);
                v2 = fmaxf(v2, 0.f); v3 = fmaxf(v3, 0.f);
            }
            *(float2*)(C + (size_t)r * NN + c) = make_float2(v0, v1);
            *(float2*)(C + (size_t)(r + 8) * NN + c) = make_float2(v2, v3);
        }
    }
}

// ---------------- mention & context pooling ----------------
__global__ void mention_ctx_kernel(const float* __restrict__ txt,
                                   const int* __restrict__ starts,
                                   const int* __restrict__ lens) {
    int m = blockIdx.x;
    int d = threadIdx.x;
    int s = starts[m], L = lens[m], e = s + L;
    float acc = 0.f;
    for (int r = s; r <= e; r++) acc += txt[(size_t)r * D_DIM + d];
    g_mc[(size_t)m * D_DIM + d] = acc / (float)(L + 1);

    int cs = s - CTX_W; if (cs < 0) cs = 0;
    int ce = e + CTX_W; if (ce > S_LEN - 1) ce = S_LEN - 1;
    float a2 = 0.f;
    for (int r = cs; r < ce; r++) a2 += txt[(size_t)r * D_DIM + d];
    g_mc[(size_t)(M_MEN + m) * D_DIM + d] = a2 / (float)(ce - cs);
}

// ---------------- pack concatenated weights (transposed: [NCAT, D]) ----------------
__global__ void pack_w_kernel(const float* __restrict__ wq, const float* __restrict__ wk,
                              const float* __restrict__ wv, const float* __restrict__ rw1,
                              const float* __restrict__ uw1) {
    size_t total = (size_t)D_DIM * NCAT;
    for (size_t idx = blockIdx.x * blockDim.x + threadIdx.x; idx < total;
         idx += (size_t)gridDim.x * blockDim.x) {
        int c = (int)(idx / D_DIM);
        int k = (int)(idx % D_DIM);
        int seg = c / D_DIM;
        int j = c - seg * D_DIM;
        float top, bot;
        if (seg == 0)      { top = bot = wq[k * D_DIM + j]; }
        else if (seg == 1) { top = bot = wk[k * D_DIM + j]; }
        else if (seg == 2) { top = bot = wv[k * D_DIM + j]; }
        else if (seg == 3) { top = rw1[k * D_DIM + j]; bot = rw1[(D_DIM + k) * D_DIM + j]; }
        else               { top = uw1[k * D_DIM + j]; bot = uw1[(D_DIM + k) * D_DIM + j]; }
        g_Wtop[idx] = top;
        g_Wbot[idx] = bot;
    }
}

// ---------------- biases only (fast) ----------------
__global__ void pack_bias_kernel(const float* __restrict__ bq, const float* __restrict__ bk,
                                 const float* __restrict__ bv, const float* __restrict__ rb1,
                                 const float* __restrict__ ub1) {
    int idx = blockIdx.x * blockDim.x + threadIdx.x;
    if (idx < NCAT) {
        int seg = idx / D_DIM;
        int j = idx - seg * D_DIM;
        float qb = (seg == 0) ? bq[j] : (seg == 1) ? bk[j] : (seg == 2) ? bv[j] : 0.f;
        g_btop[idx] = qb;
        g_bbot[idx] = (seg < 3) ? qb : (seg == 3) ? rb1[j] : ub1[j];
    }
}

// ---------------- w2bar / b2bar: warp-per-row reduction ----------------
// grid = 97 blocks x 256 threads: blocks 0..95 -> 8 rows each (one warp/row);
// block 96 -> b2bar.
__global__ void w2bar_kernel(const float* __restrict__ uw2, const float* __restrict__ ub2) {
    int lane = threadIdx.x & 31;
    int warp = threadIdx.x >> 5;
    if (blockIdx.x < 96) {
        int row = blockIdx.x * 8 + warp;
        const float* src = uw2 + (size_t)row * D_DIM;
        float s = 0.f;
#pragma unroll
        for (int j = 0; j < D_DIM / 32; j++) s += src[lane + j * 32];
#pragma unroll
        for (int sh = 16; sh; sh >>= 1) s += __shfl_down_sync(0xffffffffu, s, sh);
        if (lane == 0) g_w2bar[row] = s / (float)D_DIM;
    } else {
        __shared__ float r1[8];
        float s = 0.f;
        for (int j = threadIdx.x; j < D_DIM; j += 256) s += ub2[j];
#pragma unroll
        for (int sh = 16; sh; sh >>= 1) s += __shfl_down_sync(0xffffffffu, s, sh);
        if (lane == 0) r1[warp] = s;
        __syncthreads();
        if (threadIdx.x == 0) {
            float t = 0.f;
#pragma unroll
            for (int i = 0; i < 8; i++) t += r1[i];
            g_b2bar[0] = t / (float)D_DIM;
        }
    }
}

// ---------------- tiled transpose: out[c*R + r] = in[r*C + c] ----------------
__global__ void transpose_kernel(const float* __restrict__ in, float* __restrict__ out,
                                 int R, int Ccols) {
    __shared__ float t[32][33];
    int r0 = blockIdx.y * 32, c0 = blockIdx.x * 32;
    int x = threadIdx.x, y = threadIdx.y;   // (32, 8)
#pragma unroll
    for (int j = 0; j < 32; j += 8)
        t[y + j][x] = in[(size_t)(r0 + y + j) * Ccols + c0 + x];
    __syncthreads();
#pragma unroll
    for (int j = 0; j < 32; j += 8)
        out[(size_t)(c0 + y + j) * R + r0 + x] = t[x][y + j];
}

// ---------------- relik + unirel fused reduction ----------------
__global__ void relik_uni_kernel(const float* __restrict__ rw2,
                                 const float* __restrict__ rb2,
                                 float* __restrict__ out) {
    int p = blockIdx.x;
    int m = p >> 5;
    const float* Prel = g_Pcat + (size_t)m * NCAT + 2304;
    const float* Crel = g_Ccat + (size_t)p * NCAT + 2304;
    const float* Puni = g_Pcat + (size_t)(M_MEN + m) * NCAT + 3072;
    const float* Cuni = g_Ccat + (size_t)p * NCAT + 3072;
    int tid = threadIdx.x;
    float sr = 0.f, su = 0.f;
    for (int i = tid; i < D_DIM; i += 256) {
        sr += fmaxf(Prel[i] + Crel[i], 0.f) * rw2[i];
        su += fmaxf(Puni[i] + Cuni[i], 0.f) * g_w2bar[i];
    }
    __shared__ float r1[8], r2[8];
#pragma unroll
    for (int sh = 16; sh; sh >>= 1) {
        sr += __shfl_down_sync(0xffffffffu, sr, sh);
        su += __shfl_down_sync(0xffffffffu, su, sh);
    }
    if ((tid & 31) == 0) { r1[tid >> 5] = sr; r2[tid >> 5] = su; }
    __syncthreads();
    if (tid == 0) {
        float a = 0.f, b = 0.f;
#pragma unroll
        for (int i = 0; i < 8; i++) { a += r1[i]; b += r2[i]; }
        out[p] = a + rb2[0];
        out[2 * PAIRS + p] = 1.f / (1.f + expf(-(b + g_b2bar[0])));
    }
}

// ---------------- fused 2-token attention ----------------
__global__ void attn_kernel() {
    int p = blockIdx.x;
    int m = p >> 5;
    int w = threadIdx.x >> 5;
    int l = threadIdx.x & 31;
    const float* P0 = g_Pcat + (size_t)m * NCAT;
    const float* C1 = g_Ccat + (size_t)p * NCAT;
    int off = w * DHEAD;
    float q0v[3], k0v[3], v0v[3], q1v[3], k1v[3], v1v[3];
#pragma unroll
    for (int j = 0; j < 3; j++) {
        int d = off + l + 32 * j;
        q0v[j] = P0[d]; k0v[j] = P0[768 + d]; v0v[j] = P0[1536 + d];
        q1v[j] = C1[d]; k1v[j] = C1[768 + d]; v1v[j] = C1[1536 + d];
    }
    float s00 = 0.f, s01 = 0.f, s10 = 0.f, s11 = 0.f;
#pragma unroll
    for (int j = 0; j < 3; j++) {
        s00 += q0v[j] * k0v[j];
        s01 += q0v[j] * k1v[j];
        s10 += q1v[j] * k0v[j];
        s11 += q1v[j] * k1v[j];
    }
#pragma unroll
    for (int sh = 16; sh; sh >>= 1) {
        s00 += __shfl_xor_sync(0xffffffffu, s00, sh);
        s01 += __shfl_xor_sync(0xffffffffu, s01, sh);
        s10 += __shfl_xor_sync(0xffffffffu, s10, sh);
        s11 += __shfl_xor_sync(0xffffffffu, s11, sh);
    }
    const float sc = 0.10206207261596575f;   // 1/sqrt(96)
    float w01 = 1.f / (1.f + expf((s00 - s01) * sc));
    float w00 = 1.f - w01;
    float w11 = 1.f / (1.f + expf((s10 - s11) * sc));
    float w10 = 1.f - w11;
    float* O0 = g_O + (size_t)(2 * p) * D_DIM;
    float* O1 = O0 + D_DIM;
#pragma unroll
    for (int j = 0; j < 3; j++) {
        int d = off + l + 32 * j;
        O0[d] = w00 * v0v[j] + w01 * v1v[j];
        O1[d] = w10 * v0v[j] + w11 * v1v[j];
    }
}

// ---------------- residual + LN1 ----------------
__global__ void ln1_kernel(const float* __restrict__ cand,
                           const float* __restrict__ g, const float* __restrict__ b) {
    int r = blockIdx.x;
    int p = r >> 1, t = r & 1, m = p >> 5;
    const float* xrow = t ? (cand + (size_t)p * D_DIM) : (g_mc + (size_t)m * D_DIM);
    const float* trow = g_T + (size_t)r * D_DIM;
    int tid = threadIdx.x;
    float v[3];
    float s = 0.f, s2 = 0.f;
#pragma unroll
    for (int j = 0; j < 3; j++) {
        int i = tid + j * 256;
        v[j] = xrow[i] + trow[i];
        s += v[j];
        s2 += v[j] * v[j];
    }
    __shared__ float r1[8], r2[8];
#pragma unroll
    for (int sh = 16; sh; sh >>= 1) {
        s += __shfl_down_sync(0xffffffffu, s, sh);
        s2 += __shfl_down_sync(0xffffffffu, s2, sh);
    }
    if ((tid & 31) == 0) { r1[tid >> 5] = s; r2[tid >> 5] = s2; }
    __syncthreads();
    float tot = 0.f, tot2 = 0.f;
#pragma unroll
    for (int i = 0; i < 8; i++) { tot += r1[i]; tot2 += r2[i]; }
    float mean = tot * (1.f / 768.f);
    float var = tot2 * (1.f / 768.f) - mean * mean;
    float inv = rsqrtf(var + 1e-5f);
    float* xo = g_X1 + (size_t)r * D_DIM;
#pragma unroll
    for (int j = 0; j < 3; j++) {
        int i = tid + j * 256;
        xo[i] = (v[j] - mean) * inv * g[i] + b[i];
    }
}

// ---------------- residual + LN2 + cosine ----------------
__global__ void ln2_cos_kernel(const float* __restrict__ g, const float* __restrict__ b,
                               float* __restrict__ out) {
    int p = blockIdx.x;
    int tid = threadIdx.x;
    __shared__ float e[2][D_DIM];
    __shared__ float r1[8], r2[8], r3[8];
    for (int t = 0; t < 2; t++) {
        size_t r = (size_t)2 * p + t;
        const float* x1 = g_X1 + r * D_DIM;
        const float* gr = g_G + r * D_DIM;
        float v[3];
        float s = 0.f, s2 = 0.f;
#pragma unroll
        for (int j = 0; j < 3; j++) {
            int i = tid + j * 256;
            v[j] = x1[i] + gr[i];
            s += v[j];
            s2 += v[j] * v[j];
        }
#pragma unroll
        for (int sh = 16; sh; sh >>= 1) {
            s += __shfl_down_sync(0xffffffffu, s, sh);
            s2 += __shfl_down_sync(0xffffffffu, s2, sh);
        }
        if ((tid & 31) == 0) { r1[tid >> 5] = s; r2[tid >> 5] = s2; }
        __syncthreads();
        float tot = 0.f, tot2 = 0.f;
#pragma unroll
        for (int i = 0; i < 8; i++) { tot += r1[i]; tot2 += r2[i]; }
        float mean = tot * (1.f / 768.f);
        float var = tot2 * (1.f / 768.f) - mean * mean;
        float inv = rsqrtf(var + 1e-5f);
#pragma unroll
        for (int j = 0; j < 3; j++) {
            int i = tid + j * 256;
            e[t][i] = (v[j] - mean) * inv * g[i] + b[i];
        }
        __syncthreads();
    }
    float d = 0.f, n0 = 0.f, n1 = 0.f;
#pragma unroll
    for (int j = 0; j < 3; j++) {
        int i = tid + j * 256;
        float a = e[0][i], c = e[1][i];
        d += a * c;
        n0 += a * a;
        n1 += c * c;
    }
#pragma unroll
    for (int sh = 16; sh; sh >>= 1) {
        d += __shfl_down_sync(0xffffffffu, d, sh);
        n0 += __shfl_down_sync(0xffffffffu, n0, sh);
        n1 += __shfl_down_sync(0xffffffffu, n1, sh);
    }
    if ((tid & 31) == 0) { r1[tid >> 5] = d; r2[tid >> 5] = n0; r3[tid >> 5] = n1; }
    __syncthreads();
    if (tid == 0) {
        float td = 0.f, t0 = 0.f, t1 = 0.f;
#pragma unroll
        for (int i = 0; i < 8; i++) { td += r1[i]; t0 += r2[i]; t1 += r3[i]; }
        float na = fmaxf(sqrtf(t0), 1e-8f);
        float nb = fmaxf(sqrtf(t1), 1e-8f);
        out[PAIRS + p] = td / (na * nb);
    }
}

// ---------------- host launcher ----------------
extern "C" void kernel_launch(void* const* d_in, const int* in_sizes, int n_in,
                              void* d_out, int out_size) {
    const float* txt      = (const float*)d_in[0];
    const float* cand     = (const float*)d_in[1];
    const int*   starts   = (const int*)d_in[2];
    const int*   lens     = (const int*)d_in[3];
    const float* relik_w1 = (const float*)d_in[4];
    const float* relik_b1 = (const float*)d_in[5];
    const float* relik_w2 = (const float*)d_in[6];
    const float* relik_b2 = (const float*)d_in[7];
    const float* wq  = (const float*)d_in[8];
    const float* bq  = (const float*)d_in[9];
    const float* wk  = (const float*)d_in[10];
    const float* bk  = (const float*)d_in[11];
    const float* wv  = (const float*)d_in[12];
    const float* bv  = (const float*)d_in[13];
    const float* wo  = (const float*)d_in[14];
    const float* bo  = (const float*)d_in[15];
    const float* ln1_g = (const float*)d_in[16];
    const float* ln1_b = (const float*)d_in[17];
    const float* ffn_w1 = (const float*)d_in[18];
    const float* ffn_b1 = (const float*)d_in[19];
    const float* ffn_w2 = (const float*)d_in[20];
    const float* ffn_b2 = (const float*)d_in[21];
    const float* ln2_g = (const float*)d_in[22];
    const float* ln2_b = (const float*)d_in[23];
    const float* uni_w1 = (const float*)d_in[24];
    const float* uni_b1 = (const float*)d_in[25];
    const float* uni_w2 = (const float*)d_in[26];
    const float* uni_b2 = (const float*)d_in[27];
    float* out = (float*)d_out;

    float *p_mc, *p_Wtop, *p_Wbot, *p_btop, *p_bbot, *p_Pcat, *p_Ccat;
    float *p_O, *p_T, *p_X1, *p_F, *p_G, *p_woT, *p_f1T, *p_f2T;
    cudaGetSymbolAddress((void**)&p_mc,   g_mc);
    cudaGetSymbolAddress((void**)&p_Wtop, g_Wtop);
    cudaGetSymbolAddress((void**)&p_Wbot, g_Wbot);
    cudaGetSymbolAddress((void**)&p_btop, g_btop);
    cudaGetSymbolAddress((void**)&p_bbot, g_bbot);
    cudaGetSymbolAddress((void**)&p_Pcat, g_Pcat);
    cudaGetSymbolAddress((void**)&p_Ccat, g_Ccat);
    cudaGetSymbolAddress((void**)&p_O,    g_O);
    cudaGetSymbolAddress((void**)&p_T,    g_T);
    cudaGetSymbolAddress((void**)&p_X1,   g_X1);
    cudaGetSymbolAddress((void**)&p_F,    g_F);
    cudaGetSymbolAddress((void**)&p_G,    g_G);
    cudaGetSymbolAddress((void**)&p_woT,  g_woT);
    cudaGetSymbolAddress((void**)&p_f1T,  g_f1T);
    cudaGetSymbolAddress((void**)&p_f2T,  g_f2T);

    cudaFuncSetAttribute(tgemm_kernel,
                         cudaFuncAttributeMaxDynamicSharedMemorySize, TGEMM_SMEM);

    // Launch order arranged so launch #6 is the BIG Ccat GEMM (ncu -s 5 -c 1
    // captures it). Dependencies hold: Ccat needs cand (input) + Wbot + bbot.
    mention_ctx_kernel<<<M_MEN, D_DIM>>>(txt, starts, lens);                       // 1
    pack_w_kernel<<<4096, 256>>>(wq, wk, wv, relik_w1, uni_w1);                    // 2
    pack_bias_kernel<<<15, 256>>>(bq, bk, bv, relik_b1, uni_b1);                   // 3
    w2bar_kernel<<<97, 256>>>(uni_w2, uni_b2);                                     // 4
    transpose_kernel<<<dim3(D_DIM / 32, D_DIM / 32), dim3(32, 8)>>>(wo, p_woT, D_DIM, D_DIM); // 5
    tgemm_kernel<<<dim3(NCAT / 128, PAIRS / 128), 256, TGEMM_SMEM>>>(              // 6 (BIG)
        PAIRS, NCAT, D_DIM, cand, p_Wbot, p_bbot, p_Ccat, 0);
    tgemm_kernel<<<dim3(NCAT / 128, 2048 / 128), 256, TGEMM_SMEM>>>(               // 7
        2048, NCAT, D_DIM, p_mc, p_Wtop, p_btop, p_Pcat, 0);
    transpose_kernel<<<dim3(FFH / 32, D_DIM / 32), dim3(32, 8)>>>(ffn_w1, p_f1T, D_DIM, FFH);
    transpose_kernel<<<dim3(D_DIM / 32, FFH / 32), dim3(32, 8)>>>(ffn_w2, p_f2T, FFH, D_DIM);

    relik_uni_kernel<<<PAIRS, 256>>>(relik_w2, relik_b2, out);

    attn_kernel<<<PAIRS, 256>>>();
    tgemm_kernel<<<dim3(D_DIM / 128, NROWS / 128), 256, TGEMM_SMEM>>>(
        NROWS, D_DIM, D_DIM, p_O, p_woT, bo, p_T, 0);
    ln1_kernel<<<NROWS, 256>>>(cand, ln1_g, ln1_b);
    tgemm_kernel<<<dim3(FFH / 128, NROWS / 128), 256, TGEMM_SMEM>>>(
        NROWS, FFH, D_DIM, p_X1, p_f1T, ffn_b1, p_F, 1);
    tgemm_kernel<<<dim3(D_DIM / 128, NROWS / 128), 256, TGEMM_SMEM>>>(
        NROWS, D_DIM, FFH, p_F, p_f2T, ffn_b2, p_G, 0);

    ln2_cos_kernel<<<PAIRS, 256>>>(ln2_g, ln2_b, out);
}